// round 13
// baseline (speedup 1.0000x reference)
#include <cuda_runtime.h>
#include <cuda_fp16.h>
#include <cstdint>

#define BATCH 8
#define S1D 2048
#define S2D 2048
#define EDIM 1024
#define PDIM 1024

#define BM 128
#define BN 128
#define BK 64

// ---------------- scratch ----------------
__device__ __half g_inh[(size_t)3 * BATCH * S1D * EDIM];   // q,k,v fp16 (96 MB)
__device__ __half g_outh[(size_t)3 * BATCH * S1D * PDIM];  // projected q,k,v fp16 (96 MB)
__device__ __half g_wh[(size_t)PDIM * EDIM];               // 2 MB
__device__ __half g_probs[(size_t)BATCH * S1D * S2D];      // exp(scores) fp16 (67 MB)
__device__ float  g_rowsum[(size_t)BATCH * S1D];           // 64 KB

__device__ __forceinline__ void mma16816(float c[4], const uint32_t a[4], const uint32_t b[2]) {
    asm volatile(
        "mma.sync.aligned.m16n8k16.row.col.f32.f16.f16.f32 "
        "{%0,%1,%2,%3}, {%4,%5,%6,%7}, {%8,%9}, {%0,%1,%2,%3};\n"
        : "+f"(c[0]), "+f"(c[1]), "+f"(c[2]), "+f"(c[3])
        : "r"(a[0]), "r"(a[1]), "r"(a[2]), "r"(a[3]), "r"(b[0]), "r"(b[1]));
}

__device__ __forceinline__ void cp16(__half* sptr, const __half* gptr) {
    uint32_t s = (uint32_t)__cvta_generic_to_shared(sptr);
    asm volatile("cp.async.cg.shared.global [%0], [%1], 16;\n" :: "r"(s), "l"(gptr));
}
#define CP_COMMIT() asm volatile("cp.async.commit_group;\n")

__device__ __forceinline__ uint32_t h2_as_u32(__half2 h) {
    return *reinterpret_cast<uint32_t*>(&h);
}

// ---------------- one k-slot load (A tile 128x64 + B tile 128x64) ----------------
// A: [M][K] fp16 k-major. B: NT: [N][K] k-major; NN: [K][N] n-major.
// Smem swizzle: 16B chunk c at row r placed at chunk (c ^ (r&7)) within 128B span.
template<int BNN>
__device__ __forceinline__ void load_slot(const __half* __restrict__ A,
                                          const __half* __restrict__ B,
                                          int lda, int ldb, int m0, int n0, int kt,
                                          int buf, __half* sm) {
    const int tid = threadIdx.x;
    const int a_r = tid >> 3, a_c = tid & 7;
    __half* SA = sm + buf * 8192;
#pragma unroll
    for (int s = 0; s < 8; s++) {
        int r = a_r + 16 * s;
        cp16(SA + r * 64 + ((a_c ^ (r & 7)) << 3),
             A + (size_t)(m0 + r) * lda + kt * 64 + a_c * 8);
    }
    __half* SB = sm + 24576 + buf * 8192;
    if (!BNN) {
#pragma unroll
        for (int s = 0; s < 8; s++) {
            int r = a_r + 16 * s;
            cp16(SB + r * 64 + ((a_c ^ (r & 7)) << 3),
                 B + (size_t)(n0 + r) * ldb + kt * 64 + a_c * 8);
        }
    } else {
        const int bn_r = tid >> 4, bn_c = tid & 15;
#pragma unroll
        for (int s = 0; s < 8; s++) {
            int r = bn_r + 8 * s;
            int pc = (bn_c & 8) | ((bn_c & 7) ^ (r & 7));
            cp16(SB + r * 128 + (pc << 3),
                 B + (size_t)(kt * 64 + r) * ldb + n0 + bn_c * 8);
        }
    }
}

// ---------------- one k-slot compute (4 warps, warp tile 64x64) ----------------
template<int BNN>
__device__ __forceinline__ void compute_kt(const __half* sm, int buf, float c[4][8][4]) {
    const int lane = threadIdx.x & 31, warp = threadIdx.x >> 5;
    const int wm = (warp & 1) * 64, wn = (warp >> 1) * 64;
    const __half* As = sm + buf * 8192;
    const __half* Bs = sm + 24576 + buf * 8192;
#pragma unroll
    for (int kk = 0; kk < 64; kk += 16) {
        uint32_t a[4][4];
#pragma unroll
        for (int i = 0; i < 4; i++) {
            int row = wm + 16 * i + (lane & 15);
            int kc = (kk >> 3) + ((lane & 16) ? 1 : 0);
            uint32_t addr = (uint32_t)__cvta_generic_to_shared(
                As + row * 64 + ((kc ^ (row & 7)) << 3));
            asm volatile("ldmatrix.sync.aligned.m8n8.x4.shared.b16 {%0,%1,%2,%3}, [%4];\n"
                         : "=r"(a[i][0]), "=r"(a[i][1]), "=r"(a[i][2]), "=r"(a[i][3])
                         : "r"(addr));
        }
        uint32_t b[8][2];
        if (!BNN) {
#pragma unroll
            for (int l = 0; l < 4; l++) {
                int row = wn + 16 * l + (lane & 7) + ((lane & 16) ? 8 : 0);
                int kc = (kk >> 3) + ((lane & 8) ? 1 : 0);
                uint32_t addr = (uint32_t)__cvta_generic_to_shared(
                    Bs + row * 64 + ((kc ^ (row & 7)) << 3));
                asm volatile("ldmatrix.sync.aligned.m8n8.x4.shared.b16 {%0,%1,%2,%3}, [%4];\n"
                             : "=r"(b[2 * l][0]), "=r"(b[2 * l][1]),
                               "=r"(b[2 * l + 1][0]), "=r"(b[2 * l + 1][1])
                             : "r"(addr));
            }
        } else {
#pragma unroll
            for (int l = 0; l < 4; l++) {
                int row = kk + (lane & 7) + ((lane & 8) ? 8 : 0);
                int cc = ((wn + 16 * l) >> 3) + ((lane & 16) ? 1 : 0);
                int pc = (cc & 8) | ((cc & 7) ^ (row & 7));
                uint32_t addr = (uint32_t)__cvta_generic_to_shared(
                    Bs + row * 128 + (pc << 3));
                asm volatile("ldmatrix.sync.aligned.m8n8.x4.trans.shared.b16 {%0,%1,%2,%3}, [%4];\n"
                             : "=r"(b[2 * l][0]), "=r"(b[2 * l][1]),
                               "=r"(b[2 * l + 1][0]), "=r"(b[2 * l + 1][1])
                             : "r"(addr));
            }
        }
#pragma unroll
        for (int i = 0; i < 4; i++)
#pragma unroll
            for (int j = 0; j < 8; j++) mma16816(c[i][j], a[i], b[j]);
    }
}

#define WAIT1() asm volatile("cp.async.wait_group 1;\n")

// ---------------- fp32 -> fp16 conversion ----------------
__global__ void __launch_bounds__(256) conv_kernel(const float* __restrict__ src,
                                                   __half* __restrict__ dst) {
    size_t i = ((size_t)blockIdx.x * 256 + threadIdx.x) * 8;
    float4 v0 = *(const float4*)(src + i);
    float4 v1 = *(const float4*)(src + i + 4);
    uint4 o;
    o.x = h2_as_u32(__floats2half2_rn(v0.x, v0.y));
    o.y = h2_as_u32(__floats2half2_rn(v0.z, v0.w));
    o.z = h2_as_u32(__floats2half2_rn(v1.x, v1.y));
    o.w = h2_as_u32(__floats2half2_rn(v1.z, v1.w));
    *(uint4*)(dst + i) = o;
}

// ---------------- zero row sums ----------------
__global__ void __launch_bounds__(256) zero_kernel() {
    g_rowsum[blockIdx.x * 256 + threadIdx.x] = 0.0f;
}

// =================================================================================
// Persistent projection: tiles (x=8 over PDIM, y=384 over 3*B*S1 rows), KT=16.
// =================================================================================
__global__ void __launch_bounds__(128, 2) proj_kernel(const float* __restrict__ bias) {
    extern __shared__ __half sm[];
    const int G = gridDim.x;
    const int TILES = 8 * 384;
    const int KT = EDIM / BK;

    int pf_tile = blockIdx.x, pf_kt = 0, s_pf = 0;
    auto issue = [&]() {
        if (pf_tile < TILES) {
            int n0 = (pf_tile & 7) * BN, m0 = (pf_tile >> 3) * BM;
            load_slot<0>(g_inh, g_wh, EDIM, EDIM, m0, n0, pf_kt, s_pf % 3, sm);
        }
        CP_COMMIT();
        s_pf++;
        if (++pf_kt == KT) { pf_kt = 0; pf_tile += G; }
    };

    issue(); issue();
    int s_cur = 0;

    const int lane = threadIdx.x & 31, warp = threadIdx.x >> 5;
    const int wm = (warp & 1) * 64, wn = (warp >> 1) * 64;
    const int g = lane >> 2, t = lane & 3;

    for (int tile = blockIdx.x; tile < TILES; tile += G) {
        float c[4][8][4] = {};
        for (int kt = 0; kt < KT; kt++) {
            WAIT1();
            __syncthreads();
            issue();
            compute_kt<0>(sm, s_cur % 3, c);
            s_cur++;
        }
        const int m0 = (tile >> 3) * BM, n0 = (tile & 7) * BN;
#pragma unroll
        for (int i = 0; i < 4; i++)
#pragma unroll
            for (int j = 0; j < 8; j++) {
                int row = m0 + wm + 16 * i + g;
                int col = n0 + wn + 8 * j + 2 * t;
                float b0 = bias[col], b1 = bias[col + 1];
                *(__half2*)(g_outh + (size_t)row * PDIM + col) =
                    __floats2half2_rn(c[i][j][0] + b0, c[i][j][1] + b1);
                *(__half2*)(g_outh + (size_t)(row + 8) * PDIM + col) =
                    __floats2half2_rn(c[i][j][2] + b0, c[i][j][3] + b1);
            }
    }
}

// =================================================================================
// Persistent scores+exp: tiles (x=16 over S2D, y=16 over S1D, z=8 batch), KT=16.
// =================================================================================
__global__ void __launch_bounds__(128, 2) scores_kernel() {
    extern __shared__ __half sm[];
    const int G = gridDim.x;
    const int TILES = 16 * 16 * BATCH;
    const int KT = PDIM / BK;

    int pf_tile = blockIdx.x, pf_kt = 0, s_pf = 0;
    auto issue = [&]() {
        if (pf_tile < TILES) {
            int n0 = (pf_tile & 15) * BN, m0 = ((pf_tile >> 4) & 15) * BM;
            size_t z = pf_tile >> 8;
            const __half* A = g_outh + z * S1D * PDIM;
            const __half* B = g_outh + ((size_t)BATCH * S1D + z * S2D) * PDIM;
            load_slot<0>(A, B, PDIM, PDIM, m0, n0, pf_kt, s_pf % 3, sm);
        }
        CP_COMMIT();
        s_pf++;
        if (++pf_kt == KT) { pf_kt = 0; pf_tile += G; }
    };

    issue(); issue();
    int s_cur = 0;

    const int lane = threadIdx.x & 31, warp = threadIdx.x >> 5;
    const int wm = (warp & 1) * 64, wn = (warp >> 1) * 64;
    const int g = lane >> 2, t = lane & 3;
    const float SC = 0.03125f;

    for (int tile = blockIdx.x; tile < TILES; tile += G) {
        float c[4][8][4] = {};
        for (int kt = 0; kt < KT; kt++) {
            WAIT1();
            __syncthreads();
            issue();
            compute_kt<0>(sm, s_cur % 3, c);
            s_cur++;
        }
        const int m0 = ((tile >> 4) & 15) * BM, n0 = (tile & 15) * BN;
        const size_t z = tile >> 8;
        __half* C = g_probs + z * S1D * S2D;

        float rs[8] = {0.f, 0.f, 0.f, 0.f, 0.f, 0.f, 0.f, 0.f};
#pragma unroll
        for (int i = 0; i < 4; i++)
#pragma unroll
            for (int j = 0; j < 8; j++) {
                int row = m0 + wm + 16 * i + g;
                int col = n0 + wn + 8 * j + 2 * t;
                float e0 = __expf(c[i][j][0] * SC), e1 = __expf(c[i][j][1] * SC);
                float e2 = __expf(c[i][j][2] * SC), e3 = __expf(c[i][j][3] * SC);
                rs[2 * i] += e0 + e1;
                rs[2 * i + 1] += e2 + e3;
                *(__half2*)(C + (size_t)row * S2D + col) = __floats2half2_rn(e0, e1);
                *(__half2*)(C + (size_t)(row + 8) * S2D + col) = __floats2half2_rn(e2, e3);
            }
#pragma unroll
        for (int r = 0; r < 8; r++) {
            rs[r] += __shfl_xor_sync(0xffffffffu, rs[r], 1);
            rs[r] += __shfl_xor_sync(0xffffffffu, rs[r], 2);
        }
        if (t == 0) {
            int rbase = (int)(z * S1D) + m0 + wm + g;
#pragma unroll
            for (int i = 0; i < 4; i++) {
                atomicAdd(g_rowsum + rbase + 16 * i, rs[2 * i]);
                atomicAdd(g_rowsum + rbase + 16 * i + 8, rs[2 * i + 1]);
            }
        }
    }
}

// =================================================================================
// Persistent output: tiles (x=8 over PDIM, y=16 over S1D, z=8 batch), KT=32, NN.
// =================================================================================
__global__ void __launch_bounds__(128, 2) out_kernel(float* __restrict__ OUT) {
    extern __shared__ __half sm[];
    const int G = gridDim.x;
    const int TILES = 8 * 16 * BATCH;
    const int KT = S2D / BK;

    int pf_tile = blockIdx.x, pf_kt = 0, s_pf = 0;
    auto issue = [&]() {
        if (pf_tile < TILES) {
            int n0 = (pf_tile & 7) * BN, m0 = ((pf_tile >> 3) & 15) * BM;
            size_t z = pf_tile >> 7;
            const __half* A = g_probs + z * S1D * S2D;
            const __half* B = g_outh + ((size_t)2 * BATCH * S1D + z * S2D) * PDIM;
            load_slot<1>(A, B, S2D, PDIM, m0, n0, pf_kt, s_pf % 3, sm);
        }
        CP_COMMIT();
        s_pf++;
        if (++pf_kt == KT) { pf_kt = 0; pf_tile += G; }
    };

    issue(); issue();
    int s_cur = 0;

    const int lane = threadIdx.x & 31, warp = threadIdx.x >> 5;
    const int wm = (warp & 1) * 64, wn = (warp >> 1) * 64;
    const int g = lane >> 2, t = lane & 3;

    for (int tile = blockIdx.x; tile < TILES; tile += G) {
        float c[4][8][4] = {};
        for (int kt = 0; kt < KT; kt++) {
            WAIT1();
            __syncthreads();
            issue();
            compute_kt<1>(sm, s_cur % 3, c);
            s_cur++;
        }
        const int m0 = ((tile >> 3) & 15) * BM, n0 = (tile & 7) * BN;
        const size_t z = tile >> 7;
        float* C = OUT + z * S1D * PDIM;

        const int rbase = (int)(z * S1D) + m0 + wm + g;
        float inv[8];
#pragma unroll
        for (int i = 0; i < 4; i++) {
            inv[2 * i] = 1.0f / __ldg(g_rowsum + rbase + 16 * i);
            inv[2 * i + 1] = 1.0f / __ldg(g_rowsum + rbase + 16 * i + 8);
        }
#pragma unroll
        for (int i = 0; i < 4; i++)
#pragma unroll
            for (int j = 0; j < 8; j++) {
                int row = m0 + wm + 16 * i + g;
                int col = n0 + wn + 8 * j + 2 * t;
                *(float2*)(C + (size_t)row * PDIM + col) =
                    make_float2(c[i][j][0] * inv[2 * i], c[i][j][1] * inv[2 * i]);
                *(float2*)(C + (size_t)(row + 8) * PDIM + col) =
                    make_float2(c[i][j][2] * inv[2 * i + 1], c[i][j][3] * inv[2 * i + 1]);
            }
    }
}

// ---------------- launch ----------------
extern "C" void kernel_launch(void* const* d_in, const int* in_sizes, int n_in,
                              void* d_out, int out_size) {
    const float* q = (const float*)d_in[0];
    const float* k = (const float*)d_in[1];
    const float* v = (const float*)d_in[2];
    const float* W = (const float*)d_in[3];
    const float* b = (const float*)d_in[4];
    float* out = (float*)d_out;

    static int grid_p = 0;
    if (!grid_p) {
        int dev = 0, nsm = 148;
        cudaGetDevice(&dev);
        cudaDeviceGetAttribute(&nsm, cudaDevAttrMultiProcessorCount, dev);
        grid_p = 2 * nsm;
        cudaFuncSetAttribute(proj_kernel, cudaFuncAttributeMaxDynamicSharedMemorySize, 98304);
        cudaFuncSetAttribute(scores_kernel, cudaFuncAttributeMaxDynamicSharedMemorySize, 98304);
        cudaFuncSetAttribute(out_kernel, cudaFuncAttributeMaxDynamicSharedMemorySize, 98304);
    }

    __half* inh;
    __half* wh;
    cudaGetSymbolAddress((void**)&inh, g_inh);
    cudaGetSymbolAddress((void**)&wh, g_wh);

    const size_t NT = (size_t)BATCH * S1D * EDIM;  // 16.7M per tensor
    conv_kernel<<<NT / (256 * 8), 256>>>(q, inh);
    conv_kernel<<<NT / (256 * 8), 256>>>(k, inh + NT);
    conv_kernel<<<NT / (256 * 8), 256>>>(v, inh + 2 * NT);
    conv_kernel<<<(PDIM * EDIM) / (256 * 8), 256>>>(W, wh);
    zero_kernel<<<(BATCH * S1D) / 256, 256>>>();

    proj_kernel<<<grid_p, 128, 98304>>>(b);
    scores_kernel<<<grid_p, 128, 98304>>>();
    out_kernel<<<grid_p, 128, 98304>>>(out);
}

// round 14
// speedup vs baseline: 1.0601x; 1.0601x over previous
#include <cuda_runtime.h>
#include <cuda_fp16.h>
#include <cstdint>

#define BATCH 8
#define S1D 2048
#define S2D 2048
#define EDIM 1024
#define PDIM 1024

#define BM 128
#define BN 128
#define BK 64

// ---------------- scratch ----------------
__device__ __half g_inh[(size_t)3 * BATCH * S1D * EDIM];   // q,k,v fp16 (96 MB)
__device__ __half g_outh[(size_t)3 * BATCH * S1D * PDIM];  // projected q,k,v fp16 (96 MB)
__device__ __half g_wh[(size_t)PDIM * EDIM];               // 2 MB
__device__ __half g_probs[(size_t)BATCH * S1D * S2D];      // exp(scores) fp16 (67 MB)
__device__ float  g_rowsum[(size_t)BATCH * S1D];           // 64 KB

__device__ __forceinline__ void mma16816(float c[4], const uint32_t a[4], const uint32_t b[2]) {
    asm volatile(
        "mma.sync.aligned.m16n8k16.row.col.f32.f16.f16.f32 "
        "{%0,%1,%2,%3}, {%4,%5,%6,%7}, {%8,%9}, {%0,%1,%2,%3};\n"
        : "+f"(c[0]), "+f"(c[1]), "+f"(c[2]), "+f"(c[3])
        : "r"(a[0]), "r"(a[1]), "r"(a[2]), "r"(a[3]), "r"(b[0]), "r"(b[1]));
}

__device__ __forceinline__ void cp16(__half* sptr, const __half* gptr) {
    uint32_t s = (uint32_t)__cvta_generic_to_shared(sptr);
    asm volatile("cp.async.cg.shared.global [%0], [%1], 16;\n" :: "r"(s), "l"(gptr));
}
#define CP_COMMIT() asm volatile("cp.async.commit_group;\n")

__device__ __forceinline__ uint32_t h2_as_u32(__half2 h) {
    return *reinterpret_cast<uint32_t*>(&h);
}

// ---------------- register fragment set for one kk-step (warp tile 64x64) ----------
struct Frags {
    uint32_t a[4][4];
    uint32_t b[8][2];
};

// load fragments for k-offset kk (0,16,32,48) from stage buffer
template<int BNN>
__device__ __forceinline__ void load_frags(const __half* As, const __half* Bs,
                                           int kk, int wm, int wn, int lane, Frags& f) {
#pragma unroll
    for (int i = 0; i < 4; i++) {
        int row = wm + 16 * i + (lane & 15);
        int kc = (kk >> 3) + ((lane & 16) ? 1 : 0);
        uint32_t addr = (uint32_t)__cvta_generic_to_shared(
            As + row * 64 + ((kc ^ (row & 7)) << 3));
        asm volatile("ldmatrix.sync.aligned.m8n8.x4.shared.b16 {%0,%1,%2,%3}, [%4];\n"
                     : "=r"(f.a[i][0]), "=r"(f.a[i][1]), "=r"(f.a[i][2]), "=r"(f.a[i][3])
                     : "r"(addr));
    }
    if (!BNN) {
#pragma unroll
        for (int l = 0; l < 4; l++) {
            int row = wn + 16 * l + (lane & 7) + ((lane & 16) ? 8 : 0);
            int kc = (kk >> 3) + ((lane & 8) ? 1 : 0);
            uint32_t addr = (uint32_t)__cvta_generic_to_shared(
                Bs + row * 64 + ((kc ^ (row & 7)) << 3));
            asm volatile("ldmatrix.sync.aligned.m8n8.x4.shared.b16 {%0,%1,%2,%3}, [%4];\n"
                         : "=r"(f.b[2 * l][0]), "=r"(f.b[2 * l][1]),
                           "=r"(f.b[2 * l + 1][0]), "=r"(f.b[2 * l + 1][1])
                         : "r"(addr));
        }
    } else {
#pragma unroll
        for (int l = 0; l < 4; l++) {
            int row = kk + (lane & 7) + ((lane & 8) ? 8 : 0);
            int cc = ((wn + 16 * l) >> 3) + ((lane & 16) ? 1 : 0);
            int pc = (cc & 8) | ((cc & 7) ^ (row & 7));
            uint32_t addr = (uint32_t)__cvta_generic_to_shared(
                Bs + row * 128 + (pc << 3));
            asm volatile("ldmatrix.sync.aligned.m8n8.x4.trans.shared.b16 {%0,%1,%2,%3}, [%4];\n"
                         : "=r"(f.b[2 * l][0]), "=r"(f.b[2 * l][1]),
                           "=r"(f.b[2 * l + 1][0]), "=r"(f.b[2 * l + 1][1])
                         : "r"(addr));
        }
    }
}

__device__ __forceinline__ void mma_frags(const Frags& f, float c[4][8][4]) {
#pragma unroll
    for (int i = 0; i < 4; i++)
#pragma unroll
        for (int j = 0; j < 8; j++) mma16816(c[i][j], f.a[i], f.b[j]);
}

// =================================================================================
// GEMM mainloop. Block tile 128x128, BK=64, 4 warps (warp tile 64x64), 3-stage
// cp.async smem pipeline + 2-deep register fragment pipeline, fp32 accumulators.
// A: [M][K] fp16 k-major. B: NT: [N][K] k-major; NN: [K][N] n-major.
// Smem swizzle: 16B chunk c at row r placed at chunk (c ^ (r&7)) within 128B span.
// =================================================================================
template<int BNN>
__device__ __forceinline__ void gemm_main(const __half* __restrict__ A,
                                          const __half* __restrict__ B,
                                          int lda, int ldb, int m0, int n0, int KT,
                                          __half* sm, float c[4][8][4]) {
    const int tid = threadIdx.x;
    const int warp = tid >> 5, lane = tid & 31;
    const int wm = (warp & 1) * 64, wn = (warp >> 1) * 64;
    __half* As0 = sm;           // 3 x 8192 halves (16KB/stage)
    __half* Bs0 = sm + 24576;   // 3 x 8192 halves

    const int a_r = tid >> 3, a_c = tid & 7;     // 16 rows/sweep, 8 sweeps
    const int bn_r = tid >> 4, bn_c = tid & 15;  // NN: 8 rows/sweep, 8 sweeps

#define LOAD_A(kt, buf) {                                                              \
        __half* S = As0 + (buf) * 8192;                                                \
        _Pragma("unroll")                                                              \
        for (int s = 0; s < 8; s++) {                                                  \
            int r = a_r + 16 * s;                                                      \
            cp16(S + r * 64 + ((a_c ^ (r & 7)) << 3),                                  \
                 A + (size_t)(m0 + r) * lda + (kt) * 64 + a_c * 8);                    \
        } }
#define LOAD_B(kt, buf) {                                                              \
        __half* S = Bs0 + (buf) * 8192;                                                \
        if (!BNN) {                                                                    \
            _Pragma("unroll")                                                          \
            for (int s = 0; s < 8; s++) {                                              \
                int r = a_r + 16 * s;                                                  \
                cp16(S + r * 64 + ((a_c ^ (r & 7)) << 3),                              \
                     B + (size_t)(n0 + r) * ldb + (kt) * 64 + a_c * 8);                \
            }                                                                          \
        } else {                                                                       \
            _Pragma("unroll")                                                          \
            for (int s = 0; s < 8; s++) {                                              \
                int r = bn_r + 8 * s;                                                  \
                int pc = (bn_c & 8) | ((bn_c & 7) ^ (r & 7));                          \
                cp16(S + r * 128 + (pc << 3),                                          \
                     B + (size_t)((kt) * 64 + r) * ldb + n0 + bn_c * 8);               \
            }                                                                          \
        } }

    LOAD_A(0, 0); LOAD_B(0, 0); CP_COMMIT();
    LOAD_A(1, 1); LOAD_B(1, 1); CP_COMMIT();

    Frags f[2];

    for (int kt = 0; kt < KT; kt++) {
        const int buf = kt % 3;
        if (kt + 1 < KT) asm volatile("cp.async.wait_group 1;\n");
        else             asm volatile("cp.async.wait_group 0;\n");
        __syncthreads();
        if (kt + 2 < KT) {
            const int nb = (kt + 2) % 3;
            LOAD_A(kt + 2, nb); LOAD_B(kt + 2, nb); CP_COMMIT();
        }

        const __half* As = As0 + buf * 8192;
        const __half* Bs = Bs0 + buf * 8192;

        // register-pipelined kk loop: prefetch kk+1 frags before kk's mma burst
        load_frags<BNN>(As, Bs, 0, wm, wn, lane, f[0]);
#pragma unroll
        for (int kk4 = 0; kk4 < 4; kk4++) {
            if (kk4 < 3)
                load_frags<BNN>(As, Bs, (kk4 + 1) * 16, wm, wn, lane, f[(kk4 + 1) & 1]);
            mma_frags(f[kk4 & 1], c);
        }
    }
#undef LOAD_A
#undef LOAD_B
}

// ---------------- fp32 -> fp16 conversion ----------------
__global__ void __launch_bounds__(256) conv_kernel(const float* __restrict__ src,
                                                   __half* __restrict__ dst) {
    size_t i = ((size_t)blockIdx.x * 256 + threadIdx.x) * 8;
    float4 v0 = *(const float4*)(src + i);
    float4 v1 = *(const float4*)(src + i + 4);
    uint4 o;
    o.x = h2_as_u32(__floats2half2_rn(v0.x, v0.y));
    o.y = h2_as_u32(__floats2half2_rn(v0.z, v0.w));
    o.z = h2_as_u32(__floats2half2_rn(v1.x, v1.y));
    o.w = h2_as_u32(__floats2half2_rn(v1.z, v1.w));
    *(uint4*)(dst + i) = o;
}

// ---------------- zero row sums ----------------
__global__ void __launch_bounds__(256) zero_kernel() {
    g_rowsum[blockIdx.x * 256 + threadIdx.x] = 0.0f;
}

// ---------------- projection: g_outh = g_inh @ W^T + bias ----------------
__global__ void __launch_bounds__(128, 2) proj_kernel(const float* __restrict__ bias) {
    extern __shared__ __half sm[];
    const int m0 = blockIdx.y * BM, n0 = blockIdx.x * BN;
    float c[4][8][4] = {};
    gemm_main<0>(g_inh, g_wh, EDIM, EDIM, m0, n0, EDIM / BK, sm, c);

    const int lane = threadIdx.x & 31, warp = threadIdx.x >> 5;
    const int wm = (warp & 1) * 64, wn = (warp >> 1) * 64;
    const int g = lane >> 2, t = lane & 3;
#pragma unroll
    for (int i = 0; i < 4; i++)
#pragma unroll
        for (int j = 0; j < 8; j++) {
            int row = m0 + wm + 16 * i + g;
            int col = n0 + wn + 8 * j + 2 * t;
            float b0 = bias[col], b1 = bias[col + 1];
            *(__half2*)(g_outh + (size_t)row * PDIM + col) =
                __floats2half2_rn(c[i][j][0] + b0, c[i][j][1] + b1);
            *(__half2*)(g_outh + (size_t)(row + 8) * PDIM + col) =
                __floats2half2_rn(c[i][j][2] + b0, c[i][j][3] + b1);
        }
}

// ---------------- scores+exp: g_probs = exp((Qp @ Kp^T)/32), rowsum atomics --------
__global__ void __launch_bounds__(128, 2) scores_kernel() {
    extern __shared__ __half sm[];
    const size_t z = blockIdx.z;
    const __half* A = g_outh + z * S1D * PDIM;
    const __half* B = g_outh + (size_t)BATCH * S1D * PDIM + z * S2D * PDIM;
    __half* C = g_probs + z * S1D * S2D;
    const int m0 = blockIdx.y * BM, n0 = blockIdx.x * BN;
    float c[4][8][4] = {};
    gemm_main<0>(A, B, PDIM, PDIM, m0, n0, PDIM / BK, sm, c);

    const int lane = threadIdx.x & 31, warp = threadIdx.x >> 5;
    const int wm = (warp & 1) * 64, wn = (warp >> 1) * 64;
    const int g = lane >> 2, t = lane & 3;
    const float SC = 0.03125f;

    float rs[8] = {0.f, 0.f, 0.f, 0.f, 0.f, 0.f, 0.f, 0.f};
#pragma unroll
    for (int i = 0; i < 4; i++)
#pragma unroll
        for (int j = 0; j < 8; j++) {
            int row = m0 + wm + 16 * i + g;
            int col = n0 + wn + 8 * j + 2 * t;
            float e0 = __expf(c[i][j][0] * SC), e1 = __expf(c[i][j][1] * SC);
            float e2 = __expf(c[i][j][2] * SC), e3 = __expf(c[i][j][3] * SC);
            rs[2 * i] += e0 + e1;
            rs[2 * i + 1] += e2 + e3;
            *(__half2*)(C + (size_t)row * S2D + col) = __floats2half2_rn(e0, e1);
            *(__half2*)(C + (size_t)(row + 8) * S2D + col) = __floats2half2_rn(e2, e3);
        }

#pragma unroll
    for (int r = 0; r < 8; r++) {
        rs[r] += __shfl_xor_sync(0xffffffffu, rs[r], 1);
        rs[r] += __shfl_xor_sync(0xffffffffu, rs[r], 2);
    }
    if (t == 0) {
        int rbase = (int)(z * S1D) + m0 + wm + g;
#pragma unroll
        for (int i = 0; i < 4; i++) {
            atomicAdd(g_rowsum + rbase + 16 * i, rs[2 * i]);
            atomicAdd(g_rowsum + rbase + 16 * i + 8, rs[2 * i + 1]);
        }
    }
}

// ---------------- output: O = (exp_probs @ Vp) / rowsum  (NN gemm) ----------------
__global__ void __launch_bounds__(128, 2) out_kernel(float* __restrict__ OUT) {
    extern __shared__ __half sm[];
    const size_t z = blockIdx.z;
    const __half* A = g_probs + z * S1D * S2D;
    const __half* B = g_outh + (size_t)2 * BATCH * S1D * PDIM + z * S2D * PDIM;
    float* C = OUT + z * S1D * PDIM;
    const int m0 = blockIdx.y * BM, n0 = blockIdx.x * BN;
    float c[4][8][4] = {};
    gemm_main<1>(A, B, S2D, PDIM, m0, n0, S2D / BK, sm, c);

    const int lane = threadIdx.x & 31, warp = threadIdx.x >> 5;
    const int wm = (warp & 1) * 64, wn = (warp >> 1) * 64;
    const int g = lane >> 2, t = lane & 3;

    const int rbase = (int)(z * S1D) + m0 + wm + g;
    float inv[8];
#pragma unroll
    for (int i = 0; i < 4; i++) {
        inv[2 * i] = 1.0f / __ldg(g_rowsum + rbase + 16 * i);
        inv[2 * i + 1] = 1.0f / __ldg(g_rowsum + rbase + 16 * i + 8);
    }

#pragma unroll
    for (int i = 0; i < 4; i++)
#pragma unroll
        for (int j = 0; j < 8; j++) {
            int row = m0 + wm + 16 * i + g;
            int col = n0 + wn + 8 * j + 2 * t;
            *(float2*)(C + (size_t)row * PDIM + col) =
                make_float2(c[i][j][0] * inv[2 * i], c[i][j][1] * inv[2 * i]);
            *(float2*)(C + (size_t)(row + 8) * PDIM + col) =
                make_float2(c[i][j][2] * inv[2 * i + 1], c[i][j][3] * inv[2 * i + 1]);
        }
}

// ---------------- launch ----------------
extern "C" void kernel_launch(void* const* d_in, const int* in_sizes, int n_in,
                              void* d_out, int out_size) {
    const float* q = (const float*)d_in[0];
    const float* k = (const float*)d_in[1];
    const float* v = (const float*)d_in[2];
    const float* W = (const float*)d_in[3];
    const float* b = (const float*)d_in[4];
    float* out = (float*)d_out;

    static bool attr_done = false;
    if (!attr_done) {
        cudaFuncSetAttribute(proj_kernel, cudaFuncAttributeMaxDynamicSharedMemorySize, 98304);
        cudaFuncSetAttribute(scores_kernel, cudaFuncAttributeMaxDynamicSharedMemorySize, 98304);
        cudaFuncSetAttribute(out_kernel, cudaFuncAttributeMaxDynamicSharedMemorySize, 98304);
        attr_done = true;
    }

    __half* inh;
    __half* wh;
    cudaGetSymbolAddress((void**)&inh, g_inh);
    cudaGetSymbolAddress((void**)&wh, g_wh);

    const size_t NT = (size_t)BATCH * S1D * EDIM;  // 16.7M per tensor
    conv_kernel<<<NT / (256 * 8), 256>>>(q, inh);
    conv_kernel<<<NT / (256 * 8), 256>>>(k, inh + NT);
    conv_kernel<<<NT / (256 * 8), 256>>>(v, inh + 2 * NT);
    conv_kernel<<<(PDIM * EDIM) / (256 * 8), 256>>>(W, wh);
    zero_kernel<<<(BATCH * S1D) / 256, 256>>>();

    dim3 gproj(PDIM / BN, (3 * BATCH * S1D) / BM);  // 8 x 384
    proj_kernel<<<gproj, 128, 98304>>>(b);

    dim3 gs(S2D / BN, S1D / BM, BATCH);  // 16 x 16 x 8
    scores_kernel<<<gs, 128, 98304>>>();

    dim3 go(PDIM / BN, S1D / BM, BATCH);  // 8 x 16 x 8
    out_kernel<<<go, 128, 98304>>>(out);
}

// round 15
// speedup vs baseline: 1.1079x; 1.0451x over previous
#include <cuda_runtime.h>
#include <cuda_fp16.h>
#include <cstdint>

#define BATCH 8
#define S1D 2048
#define S2D 2048
#define EDIM 1024
#define PDIM 1024

#define BM 128
#define BN 128
#define BK 64

// ---------------- scratch ----------------
__device__ __half g_inh[(size_t)3 * BATCH * S1D * EDIM];   // q,k,v fp16 (96 MB)
__device__ __half g_outh[(size_t)3 * BATCH * S1D * PDIM];  // projected q,k,v fp16 (96 MB)
__device__ __half g_wh[(size_t)PDIM * EDIM];               // 2 MB
__device__ __half g_probs[(size_t)BATCH * S1D * S2D];      // exp(scores) fp16 (67 MB)
__device__ float  g_rowsum[(size_t)BATCH * S1D];           // 64 KB

__device__ __forceinline__ void mma16816(float c[4], const uint32_t a[4], const uint32_t b[2]) {
    asm volatile(
        "mma.sync.aligned.m16n8k16.row.col.f32.f16.f16.f32 "
        "{%0,%1,%2,%3}, {%4,%5,%6,%7}, {%8,%9}, {%0,%1,%2,%3};\n"
        : "+f"(c[0]), "+f"(c[1]), "+f"(c[2]), "+f"(c[3])
        : "r"(a[0]), "r"(a[1]), "r"(a[2]), "r"(a[3]), "r"(b[0]), "r"(b[1]));
}

__device__ __forceinline__ void cp16(__half* sptr, const __half* gptr) {
    uint32_t s = (uint32_t)__cvta_generic_to_shared(sptr);
    asm volatile("cp.async.cg.shared.global [%0], [%1], 16;\n" :: "r"(s), "l"(gptr));
}
#define CP_COMMIT() asm volatile("cp.async.commit_group;\n")

__device__ __forceinline__ uint32_t h2_as_u32(__half2 h) {
    return *reinterpret_cast<uint32_t*>(&h);
}

// ---------------- register fragment set for one kk-step (warp tile 64x64) ----------
struct Frags {
    uint32_t a[4][4];
    uint32_t b[8][2];
};

template<int BNN>
__device__ __forceinline__ void load_frags(const __half* As, const __half* Bs,
                                           int kk, int wm, int wn, int lane, Frags& f) {
#pragma unroll
    for (int i = 0; i < 4; i++) {
        int row = wm + 16 * i + (lane & 15);
        int kc = (kk >> 3) + ((lane & 16) ? 1 : 0);
        uint32_t addr = (uint32_t)__cvta_generic_to_shared(
            As + row * 64 + ((kc ^ (row & 7)) << 3));
        asm volatile("ldmatrix.sync.aligned.m8n8.x4.shared.b16 {%0,%1,%2,%3}, [%4];\n"
                     : "=r"(f.a[i][0]), "=r"(f.a[i][1]), "=r"(f.a[i][2]), "=r"(f.a[i][3])
                     : "r"(addr));
    }
    if (!BNN) {
#pragma unroll
        for (int l = 0; l < 4; l++) {
            int row = wn + 16 * l + (lane & 7) + ((lane & 16) ? 8 : 0);
            int kc = (kk >> 3) + ((lane & 8) ? 1 : 0);
            uint32_t addr = (uint32_t)__cvta_generic_to_shared(
                Bs + row * 64 + ((kc ^ (row & 7)) << 3));
            asm volatile("ldmatrix.sync.aligned.m8n8.x4.shared.b16 {%0,%1,%2,%3}, [%4];\n"
                         : "=r"(f.b[2 * l][0]), "=r"(f.b[2 * l][1]),
                           "=r"(f.b[2 * l + 1][0]), "=r"(f.b[2 * l + 1][1])
                         : "r"(addr));
        }
    } else {
#pragma unroll
        for (int l = 0; l < 4; l++) {
            int row = kk + (lane & 7) + ((lane & 8) ? 8 : 0);
            int cc = ((wn + 16 * l) >> 3) + ((lane & 16) ? 1 : 0);
            int pc = (cc & 8) | ((cc & 7) ^ (row & 7));
            uint32_t addr = (uint32_t)__cvta_generic_to_shared(
                Bs + row * 128 + (pc << 3));
            asm volatile("ldmatrix.sync.aligned.m8n8.x4.trans.shared.b16 {%0,%1,%2,%3}, [%4];\n"
                         : "=r"(f.b[2 * l][0]), "=r"(f.b[2 * l][1]),
                           "=r"(f.b[2 * l + 1][0]), "=r"(f.b[2 * l + 1][1])
                         : "r"(addr));
        }
    }
}

__device__ __forceinline__ void mma_frags(const Frags& f, float c[4][8][4]) {
#pragma unroll
    for (int i = 0; i < 4; i++)
#pragma unroll
        for (int j = 0; j < 8; j++) mma16816(c[i][j], f.a[i], f.b[j]);
}

// =================================================================================
// GEMM mainloop. Block tile 128x128, BK=64, 4 warps (warp tile 64x64), 3-stage
// cp.async smem pipeline + 2-deep register fragment pipeline, fp32 accumulators.
// cp.async issue for kt+2 is spread through the kk loop (1/4 per kk-step) so the
// LSU is not monopolized right when ldmatrix needs it.
// A: [M][K] fp16 k-major. B: NT: [N][K] k-major; NN: [K][N] n-major.
// Smem swizzle: 16B chunk c at row r placed at chunk (c ^ (r&7)) within 128B span.
// =================================================================================
template<int BNN>
__device__ __forceinline__ void gemm_main(const __half* __restrict__ A,
                                          const __half* __restrict__ B,
                                          int lda, int ldb, int m0, int n0, int KT,
                                          __half* sm, float c[4][8][4]) {
    const int tid = threadIdx.x;
    const int warp = tid >> 5, lane = tid & 31;
    const int wm = (warp & 1) * 64, wn = (warp >> 1) * 64;
    __half* As0 = sm;           // 3 x 8192 halves (16KB/stage)
    __half* Bs0 = sm + 24576;   // 3 x 8192 halves

    const int a_r = tid >> 3, a_c = tid & 7;     // 16 rows/sweep, 8 sweeps
    const int bn_r = tid >> 4, bn_c = tid & 15;  // NN: 8 rows/sweep, 8 sweeps

    // quarter-load: sweeps s = 2*qq, 2*qq+1 of A and B
#define LOAD_Q(kt, buf, qq) {                                                          \
        __half* SA = As0 + (buf) * 8192;                                               \
        __half* SB = Bs0 + (buf) * 8192;                                               \
        _Pragma("unroll")                                                              \
        for (int u = 0; u < 2; u++) {                                                  \
            int r = a_r + 16 * (2 * (qq) + u);                                         \
            cp16(SA + r * 64 + ((a_c ^ (r & 7)) << 3),                                 \
                 A + (size_t)(m0 + r) * lda + (kt) * 64 + a_c * 8);                    \
        }                                                                              \
        if (!BNN) {                                                                    \
            _Pragma("unroll")                                                          \
            for (int u = 0; u < 2; u++) {                                              \
                int r = a_r + 16 * (2 * (qq) + u);                                     \
                cp16(SB + r * 64 + ((a_c ^ (r & 7)) << 3),                             \
                     B + (size_t)(n0 + r) * ldb + (kt) * 64 + a_c * 8);                \
            }                                                                          \
        } else {                                                                       \
            _Pragma("unroll")                                                          \
            for (int u = 0; u < 2; u++) {                                              \
                int r = bn_r + 8 * (2 * (qq) + u);                                     \
                int pc = (bn_c & 8) | ((bn_c & 7) ^ (r & 7));                          \
                cp16(SB + r * 128 + (pc << 3),                                         \
                     B + (size_t)((kt) * 64 + r) * ldb + n0 + bn_c * 8);               \
            }                                                                          \
        } }

    // prologue: full loads for kt=0,1
#pragma unroll
    for (int qq = 0; qq < 4; qq++) LOAD_Q(0, 0, qq);
    CP_COMMIT();
#pragma unroll
    for (int qq = 0; qq < 4; qq++) LOAD_Q(1, 1, qq);
    CP_COMMIT();

    Frags f[2];

    for (int kt = 0; kt < KT; kt++) {
        const int buf = kt % 3;
        asm volatile("cp.async.wait_group 1;\n");
        __syncthreads();

        const __half* As = As0 + buf * 8192;
        const __half* Bs = Bs0 + buf * 8192;
        const bool pf = (kt + 2 < KT);
        const int nb = (kt + 2) % 3;

        load_frags<BNN>(As, Bs, 0, wm, wn, lane, f[0]);
#pragma unroll
        for (int kk4 = 0; kk4 < 4; kk4++) {
            if (pf) LOAD_Q(kt + 2, nb, kk4);
            if (kk4 < 3)
                load_frags<BNN>(As, Bs, (kk4 + 1) * 16, wm, wn, lane, f[(kk4 + 1) & 1]);
            mma_frags(f[kk4 & 1], c);
        }
        CP_COMMIT();   // one group per kt (possibly empty near the tail)
    }
#undef LOAD_Q
}

// ---------------- fused fp32->fp16 conversion (q|k|v|W) + rowsum zero ----------------
__global__ void __launch_bounds__(256) conv_all_kernel(const float* __restrict__ q,
                                                       const float* __restrict__ k,
                                                       const float* __restrict__ v,
                                                       const float* __restrict__ W) {
    const size_t NT = (size_t)BATCH * S1D * EDIM;
    size_t gid = (size_t)blockIdx.x * 256 + threadIdx.x;
    size_t i = gid * 8;
    const float* src;
    __half* dst;
    size_t off;
    if (i < NT)            { src = q; dst = g_inh;          off = i; }
    else if (i < 2 * NT)   { src = k; dst = g_inh + NT;     off = i - NT; }
    else if (i < 3 * NT)   { src = v; dst = g_inh + 2 * NT; off = i - 2 * NT; }
    else                   { src = W; dst = g_wh;           off = i - 3 * NT; }
    float4 v0 = *(const float4*)(src + off);
    float4 v1 = *(const float4*)(src + off + 4);
    uint4 o;
    o.x = h2_as_u32(__floats2half2_rn(v0.x, v0.y));
    o.y = h2_as_u32(__floats2half2_rn(v0.z, v0.w));
    o.z = h2_as_u32(__floats2half2_rn(v1.x, v1.y));
    o.w = h2_as_u32(__floats2half2_rn(v1.z, v1.w));
    *(uint4*)(dst + off) = o;
    if (gid < (size_t)BATCH * S1D) g_rowsum[gid] = 0.0f;
}

// ---------------- projection: g_outh = g_inh @ W^T + bias ----------------
__global__ void __launch_bounds__(128, 2) proj_kernel(const float* __restrict__ bias) {
    extern __shared__ __half sm[];
    const int m0 = blockIdx.y * BM, n0 = blockIdx.x * BN;
    float c[4][8][4] = {};
    gemm_main<0>(g_inh, g_wh, EDIM, EDIM, m0, n0, EDIM / BK, sm, c);

    const int lane = threadIdx.x & 31, warp = threadIdx.x >> 5;
    const int wm = (warp & 1) * 64, wn = (warp >> 1) * 64;
    const int g = lane >> 2, t = lane & 3;
#pragma unroll
    for (int i = 0; i < 4; i++)
#pragma unroll
        for (int j = 0; j < 8; j++) {
            int row = m0 + wm + 16 * i + g;
            int col = n0 + wn + 8 * j + 2 * t;
            float b0 = bias[col], b1 = bias[col + 1];
            *(__half2*)(g_outh + (size_t)row * PDIM + col) =
                __floats2half2_rn(c[i][j][0] + b0, c[i][j][1] + b1);
            *(__half2*)(g_outh + (size_t)(row + 8) * PDIM + col) =
                __floats2half2_rn(c[i][j][2] + b0, c[i][j][3] + b1);
        }
}

// ---------------- scores+exp: g_probs = exp((Qp @ Kp^T)/32), rowsum atomics --------
__global__ void __launch_bounds__(128, 2) scores_kernel() {
    extern __shared__ __half sm[];
    const size_t z = blockIdx.z;
    const __half* A = g_outh + z * S1D * PDIM;
    const __half* B = g_outh + (size_t)BATCH * S1D * PDIM + z * S2D * PDIM;
    __half* C = g_probs + z * S1D * S2D;
    const int m0 = blockIdx.y * BM, n0 = blockIdx.x * BN;
    float c[4][8][4] = {};
    gemm_main<0>(A, B, PDIM, PDIM, m0, n0, PDIM / BK, sm, c);

    const int lane = threadIdx.x & 31, warp = threadIdx.x >> 5;
    const int wm = (warp & 1) * 64, wn = (warp >> 1) * 64;
    const int g = lane >> 2, t = lane & 3;
    const float SC = 0.03125f;

    float rs[8] = {0.f, 0.f, 0.f, 0.f, 0.f, 0.f, 0.f, 0.f};
#pragma unroll
    for (int i = 0; i < 4; i++)
#pragma unroll
        for (int j = 0; j < 8; j++) {
            int row = m0 + wm + 16 * i + g;
            int col = n0 + wn + 8 * j + 2 * t;
            float e0 = __expf(c[i][j][0] * SC), e1 = __expf(c[i][j][1] * SC);
            float e2 = __expf(c[i][j][2] * SC), e3 = __expf(c[i][j][3] * SC);
            rs[2 * i] += e0 + e1;
            rs[2 * i + 1] += e2 + e3;
            *(__half2*)(C + (size_t)row * S2D + col) = __floats2half2_rn(e0, e1);
            *(__half2*)(C + (size_t)(row + 8) * S2D + col) = __floats2half2_rn(e2, e3);
        }

#pragma unroll
    for (int r = 0; r < 8; r++) {
        rs[r] += __shfl_xor_sync(0xffffffffu, rs[r], 1);
        rs[r] += __shfl_xor_sync(0xffffffffu, rs[r], 2);
    }
    if (t == 0) {
        int rbase = (int)(z * S1D) + m0 + wm + g;
#pragma unroll
        for (int i = 0; i < 4; i++) {
            atomicAdd(g_rowsum + rbase + 16 * i, rs[2 * i]);
            atomicAdd(g_rowsum + rbase + 16 * i + 8, rs[2 * i + 1]);
        }
    }
}

// ---------------- output: O = (exp_probs @ Vp) / rowsum  (NN gemm) ----------------
__global__ void __launch_bounds__(128, 2) out_kernel(float* __restrict__ OUT) {
    extern __shared__ __half sm[];
    const size_t z = blockIdx.z;
    const __half* A = g_probs + z * S1D * S2D;
    const __half* B = g_outh + (size_t)2 * BATCH * S1D * PDIM + z * S2D * PDIM;
    float* C = OUT + z * S1D * PDIM;
    const int m0 = blockIdx.y * BM, n0 = blockIdx.x * BN;
    float c[4][8][4] = {};
    gemm_main<1>(A, B, S2D, PDIM, m0, n0, S2D / BK, sm, c);

    const int lane = threadIdx.x & 31, warp = threadIdx.x >> 5;
    const int wm = (warp & 1) * 64, wn = (warp >> 1) * 64;
    const int g = lane >> 2, t = lane & 3;

    const int rbase = (int)(z * S1D) + m0 + wm + g;
    float inv[8];
#pragma unroll
    for (int i = 0; i < 4; i++) {
        inv[2 * i] = 1.0f / __ldg(g_rowsum + rbase + 16 * i);
        inv[2 * i + 1] = 1.0f / __ldg(g_rowsum + rbase + 16 * i + 8);
    }

#pragma unroll
    for (int i = 0; i < 4; i++)
#pragma unroll
        for (int j = 0; j < 8; j++) {
            int row = m0 + wm + 16 * i + g;
            int col = n0 + wn + 8 * j + 2 * t;
            *(float2*)(C + (size_t)row * PDIM + col) =
                make_float2(c[i][j][0] * inv[2 * i], c[i][j][1] * inv[2 * i]);
            *(float2*)(C + (size_t)(row + 8) * PDIM + col) =
                make_float2(c[i][j][2] * inv[2 * i + 1], c[i][j][3] * inv[2 * i + 1]);
        }
}

// ---------------- launch ----------------
extern "C" void kernel_launch(void* const* d_in, const int* in_sizes, int n_in,
                              void* d_out, int out_size) {
    const float* q = (const float*)d_in[0];
    const float* k = (const float*)d_in[1];
    const float* v = (const float*)d_in[2];
    const float* W = (const float*)d_in[3];
    const float* b = (const float*)d_in[4];
    float* out = (float*)d_out;

    static bool attr_done = false;
    if (!attr_done) {
        cudaFuncSetAttribute(proj_kernel, cudaFuncAttributeMaxDynamicSharedMemorySize, 98304);
        cudaFuncSetAttribute(scores_kernel, cudaFuncAttributeMaxDynamicSharedMemorySize, 98304);
        cudaFuncSetAttribute(out_kernel, cudaFuncAttributeMaxDynamicSharedMemorySize, 98304);
        attr_done = true;
    }

    const size_t NT = (size_t)BATCH * S1D * EDIM;  // 16.7M per tensor
    const size_t TOT = 3 * NT + (size_t)PDIM * EDIM;
    conv_all_kernel<<<(unsigned)(TOT / (256 * 8)), 256>>>(q, k, v, W);

    dim3 gproj(PDIM / BN, (3 * BATCH * S1D) / BM);  // 8 x 384
    proj_kernel<<<gproj, 128, 98304>>>(b);

    dim3 gs(S2D / BN, S1D / BM, BATCH);  // 16 x 16 x 8
    scores_kernel<<<gs, 128, 98304>>>();

    dim3 go(PDIM / BN, S1D / BM, BATCH);  // 8 x 16 x 8
    out_kernel<<<go, 128, 98304>>>(out);
}